// round 4
// baseline (speedup 1.0000x reference)
#include <cuda_runtime.h>
#include <cstdint>

#define SEQ 262144
#define HID 20

union F2U { float2 f; unsigned long long u; };
__device__ __forceinline__ float2 ffma2(float2 a, float2 b, float2 c) {
    F2U A, B, C, R; A.f = a; B.f = b; C.f = c;
    asm("fma.rn.f32x2 %0, %1, %2, %3;" : "=l"(R.u) : "l"(A.u), "l"(B.u), "l"(C.u));
    return R.f;
}
__device__ __forceinline__ float ex2f(float x) {
    float r; asm("ex2.approx.f32 %0, %1;" : "=f"(r) : "f"(x)); return r;
}
__device__ __forceinline__ float rcpf(float x) {
    float r; asm("rcp.approx.f32 %0, %1;" : "=f"(r) : "f"(x)); return r;
}
__device__ __forceinline__ float tanh_fast(float x) {
    return fmaf(rcpf(1.f + ex2f(x * -2.885390082f)), 2.f, -1.f);
}

__global__ void __launch_bounds__(192, 1) lstm_scan_kernel(
    const float* __restrict__ x,
    const float* __restrict__ w_ih1, const float* __restrict__ w_hh1, const float* __restrict__ b1,
    const float* __restrict__ w_ih2, const float* __restrict__ w_hh2, const float* __restrict__ b2,
    const float* __restrict__ w_p,  const float* __restrict__ b_p,
    float* __restrict__ out)
{
    // x ring: 32 steps × 12 floats (9 used) + 12 guard floats (A-loop overreads ×0 weights)
    __shared__ __align__(16) float xflat[32 * 12 + 12];
    __shared__ __align__(16) float h1buf[2][24];
    __shared__ __align__(16) float h2buf[2][24];

    const int tid  = threadIdx.x;
    const int lane = tid & 31;
    const int qb   = lane & ~3;
    const bool isGate = tid < 160;

    // ---- per-lane weights ----
    float2 wa[10], wb[10];
    float  bias = 0.f, escale = -1.4426950408f, amul = 1.f, aadd = 0.f;
    int    layer = 0, u = 0, gate = 0;

    if (isGate) {
        layer = (tid >= 80);
        const int gl = layer ? tid - 80 : tid;
        u = gl >> 2;
        gate = tid & 3;                      // quads aligned: 0=i 1=f 2=g 3=o
        const int r = gate * HID + u;
        if (!layer) {
            const float* Wx = w_ih1 + r * 9;
            wa[0] = make_float2(Wx[0], Wx[1]); wa[1] = make_float2(Wx[2], Wx[3]);
            wa[2] = make_float2(Wx[4], Wx[5]); wa[3] = make_float2(Wx[6], Wx[7]);
            wa[4] = make_float2(Wx[8], 0.f);
            #pragma unroll
            for (int k = 5; k < 10; k++) wa[k] = make_float2(0.f, 0.f);
            const float2* Wh = (const float2*)(w_hh1 + r * HID);
            #pragma unroll
            for (int k = 0; k < 10; k++) wb[k] = Wh[k];
            bias = b1[r];
        } else {
            const float2* Wi = (const float2*)(w_ih2 + r * HID);
            const float2* Wh = (const float2*)(w_hh2 + r * HID);
            #pragma unroll
            for (int k = 0; k < 10; k++) { wa[k] = Wi[k]; wb[k] = Wh[k]; }
            bias = b2[r];
        }
        if (gate == 2) { escale = -2.885390082f; amul = 2.f; aadd = -1.f; }
    }
    float wp = 0.f;
    if (!isGate && lane < HID) wp = w_p[lane];
    const float bp = b_p[0];

    // ---- zero-init shared ----
    for (int i = tid; i < 32 * 12 + 12; i += 192) xflat[i] = 0.f;
    if (tid < 24) { h1buf[0][tid] = 0.f; h1buf[1][tid] = 0.f; h2buf[0][tid] = 0.f; h2buf[1][tid] = 0.f; }
    __syncthreads();

    // ---- preload x steps 0..31 (warp 5) ----
    if (!isGate) {
        #pragma unroll
        for (int base = 0; base < 2; base++) {
            const int g0 = base * 144;
            #pragma unroll
            for (int j = 0; j < 5; j++) {
                const int idx = lane + 32 * j;
                if (idx < 144) {
                    const float v = x[g0 + idx];
                    const int s = idx / 9, k = idx - s * 9;
                    xflat[(base * 16 + s) * 12 + k] = v;
                }
            }
        }
    }
    __syncthreads();

    // ---- parity-constant pointers ----
    const float2* A_l2[2] = { nullptr, nullptr };
    const float2* Bp_[2]  = { nullptr, nullptr };
    float* Sp_[2] = { nullptr, nullptr };
    int tminS = 0, tmaxS = 0, tminC = 0;
    if (isGate) {
        if (!layer) {
            Bp_[0] = (const float2*)h1buf[1]; Bp_[1] = (const float2*)h1buf[0];
            Sp_[0] = &h1buf[0][u];            Sp_[1] = &h1buf[1][u];
            tminS = 0; tmaxS = SEQ; tminC = 0;
        } else {
            A_l2[0] = (const float2*)h1buf[1]; A_l2[1] = (const float2*)h1buf[0];
            Bp_[0]  = (const float2*)h2buf[0]; Bp_[1]  = (const float2*)h2buf[1];
            Sp_[0]  = &h2buf[1][u];            Sp_[1]  = &h2buf[0][u];
            tminS = 1; tmaxS = SEQ + 1; tminC = 1;
        }
    }

    float c = 0.f;
    const float2 ONE2 = make_float2(1.f, 1.f);

#define STEP(T, P) do {                                                          \
    if (isGate) {                                                                \
        const float2* Ap = layer ? A_l2[P]                                       \
                                 : (const float2*)(xflat + ((T) & 31) * 12);     \
        const float2* Bq = Bp_[P];                                               \
        float2 a0 = make_float2(bias, 0.f), a1 = make_float2(0.f, 0.f);          \
        float2 a2 = make_float2(0.f, 0.f),  a3 = make_float2(0.f, 0.f);          \
        _Pragma("unroll")                                                        \
        for (int k = 0; k < 10; k += 2) {                                        \
            a0 = ffma2(wa[k],   Ap[k],   a0);                                    \
            a1 = ffma2(wa[k+1], Ap[k+1], a1);                                    \
        }                                                                        \
        _Pragma("unroll")                                                        \
        for (int k = 0; k < 10; k += 2) {                                        \
            a2 = ffma2(wb[k],   Bq[k],   a2);                                    \
            a3 = ffma2(wb[k+1], Bq[k+1], a3);                                    \
        }                                                                        \
        a0 = ffma2(ONE2, a1, a0); a2 = ffma2(ONE2, a3, a2);                      \
        a0 = ffma2(ONE2, a2, a0);                                                \
        const float v   = a0.x + a0.y;                                           \
        const float act = fmaf(rcpf(1.f + ex2f(v * escale)), amul, aadd);        \
        const float gi = __shfl_sync(0xffffffffu, act, qb);                      \
        const float gf = __shfl_sync(0xffffffffu, act, qb + 1);                  \
        const float gg = __shfl_sync(0xffffffffu, act, qb + 2);                  \
        const float go = __shfl_sync(0xffffffffu, act, qb + 3);                  \
        const float nc = fmaf(gf, c, gi * gg);                                   \
        c = ((T) >= tminC) ? nc : c;                                             \
        const float h = go * tanh_fast(c);                                       \
        if (gate == 0 && (T) >= tminS && (T) < tmaxS) *Sp_[P] = h;               \
    } else {                                                                     \
        if ((T) >= 2) {                                                          \
            float hv = (lane < HID) ? h2buf[(T) & 1][lane] : 0.f;                \
            float p = wp * hv;                                                   \
            _Pragma("unroll")                                                    \
            for (int o = 16; o; o >>= 1)                                         \
                p += __shfl_down_sync(0xffffffffu, p, o);                        \
            if (lane == 0) out[(T) - 2] = p + bp;                                \
        }                                                                        \
        if ((((T) & 15) == 0) && ((T) + 16 < SEQ)) {                             \
            const int g0 = ((T) + 16) * 9;                                       \
            const int rbase = ((T) + 16) & 31;                                   \
            _Pragma("unroll")                                                    \
            for (int j = 0; j < 5; j++) {                                        \
                const int idx = lane + 32 * j;                                   \
                if (idx < 144) {                                                 \
                    const float vv = x[g0 + idx];                                \
                    const int s = idx / 9, k2 = idx - s * 9;                     \
                    xflat[(rbase + s) * 12 + k2] = vv;                           \
                }                                                                \
            }                                                                    \
        }                                                                        \
    }                                                                            \
    __syncthreads();                                                             \
} while (0)

    // iter t: L1 -> h1[t], L2 -> h2[t-1], proj -> out[t-2]
    for (int t = 0; t < SEQ + 2; t += 2) {
        STEP(t,     0);
        STEP(t + 1, 1);
    }
#undef STEP
}

extern "C" void kernel_launch(void* const* d_in, const int* in_sizes, int n_in,
                              void* d_out, int out_size) {
    (void)in_sizes; (void)n_in; (void)out_size;
    lstm_scan_kernel<<<1, 192>>>(
        (const float*)d_in[0],
        (const float*)d_in[1], (const float*)d_in[2], (const float*)d_in[3],
        (const float*)d_in[4], (const float*)d_in[5], (const float*)d_in[6],
        (const float*)d_in[7], (const float*)d_in[8],
        (float*)d_out);
}

// round 6
// speedup vs baseline: 1.5417x; 1.5417x over previous
#include <cuda_runtime.h>
#include <cstdint>

#define SEQ 262144
#define BK  16
#define NS  (SEQ / BK)   // 16384 supersteps

union F2U { float2 f; unsigned long long u; };
__device__ __forceinline__ float2 ffma2(float2 a, float2 b, float2 c) {
    F2U A, B, C, R; A.f = a; B.f = b; C.f = c;
    asm("fma.rn.f32x2 %0, %1, %2, %3;" : "=l"(R.u) : "l"(A.u), "l"(B.u), "l"(C.u));
    return R.f;
}
__device__ __forceinline__ float ex2f(float x){ float r; asm("ex2.approx.f32 %0,%1;":"=f"(r):"f"(x)); return r; }
__device__ __forceinline__ float rcpf(float x){ float r; asm("rcp.approx.f32 %0,%1;":"=f"(r):"f"(x)); return r; }
__device__ __forceinline__ float sigm_f(float x){ return rcpf(1.f + ex2f(x * -1.4426950408889634f)); }
__device__ __forceinline__ float tanh_f(float x){ return fmaf(rcpf(1.f + ex2f(x * -2.8853900817779268f)), 2.f, -1.f); }

__global__ void __launch_bounds__(128, 1) lstm_scan_kernel(
    const float* __restrict__ x,
    const float* __restrict__ w_ih1, const float* __restrict__ w_hh1, const float* __restrict__ b1,
    const float* __restrict__ w_ih2, const float* __restrict__ w_hh2, const float* __restrict__ b2,
    const float* __restrict__ w_p,  const float* __restrict__ b_p,
    float* __restrict__ out)
{
    __shared__ float xring[32][12];                       // 2 blocks of x
    __shared__ __align__(16) float xpart[2][BK][20][4];   // b1 + w_ih1·x  (per step,unit,gate)
    __shared__ __align__(16) float apart[2][BK][20][4];   // b2 + w_ih2·h1
    __shared__ __align__(8)  float h1r[32][24];
    __shared__ __align__(8)  float h2r[32][24];

    const int tid  = threadIdx.x;
    const int w    = tid >> 5;
    const int lane = tid & 31;
    const int uc   = (lane < 20) ? lane : 19;

    // ---------------- per-warp resident weights ----------------
    float2 wh[4][10];               // W0: w_hh1 rows; W2: w_hh2 rows (gate g, unit uc)
    float2 wi[3][10]; float bb[3];  // W1: w_ih2 rows r = lane + 32q
    int    au[3], ag[3], av[3];
    float2 wx[3][5];  float bx[3];  // W3: w_ih1 rows
    int    xu[3], xg[3], xv[3];
    float  wpv = 0.f;

    if (w == 0 || w == 2) {
        const float* WH = (w == 0) ? w_hh1 : w_hh2;
        #pragma unroll
        for (int g = 0; g < 4; g++) {
            const int r = g * 20 + uc;
            const float2* row = (const float2*)(WH + r * 20);
            #pragma unroll
            for (int k = 0; k < 10; k++) wh[g][k] = row[k];
        }
    } else if (w == 1) {
        #pragma unroll
        for (int q = 0; q < 3; q++) {
            const int r  = lane + 32 * q;
            const int ok = (r < 80);
            const int rc = ok ? r : 79;
            const float2* row = (const float2*)(w_ih2 + rc * 20);
            #pragma unroll
            for (int k = 0; k < 10; k++) wi[q][k] = row[k];
            bb[q] = b2[rc];
            au[q] = rc % 20; ag[q] = rc / 20; av[q] = ok;
        }
    } else {
        #pragma unroll
        for (int q = 0; q < 3; q++) {
            const int r  = lane + 32 * q;
            const int ok = (r < 80);
            const int rc = ok ? r : 79;
            const float* row = w_ih1 + rc * 9;
            wx[q][0] = make_float2(row[0], row[1]);
            wx[q][1] = make_float2(row[2], row[3]);
            wx[q][2] = make_float2(row[4], row[5]);
            wx[q][3] = make_float2(row[6], row[7]);
            wx[q][4] = make_float2(row[8], 0.f);
            bx[q] = b1[rc];
            xu[q] = rc % 20; xg[q] = rc / 20; xv[q] = ok;
        }
        if (lane < 20) wpv = w_p[lane];
    }
    const float bpv = b_p[0];

    // ---------------- zero rings ----------------
    for (int i = tid; i < 32 * 24; i += 128) { ((float*)h1r)[i] = 0.f; ((float*)h2r)[i] = 0.f; }
    for (int i = tid; i < 32 * 12; i += 128) ((float*)xring)[i] = 0.f;
    __syncthreads();

    // ---------------- prologue: x blocks 0,1 then xpart block 0 ----------------
    if (w == 3) {
        #pragma unroll
        for (int bb2 = 0; bb2 < 2; bb2++) {
            const float* src = x + bb2 * 144;
            #pragma unroll
            for (int i = 0; i < 5; i++) {
                const int idx = lane + 32 * i;
                if (idx < 144) {
                    const float v = src[idx];
                    const int st = idx / 9, k = idx - st * 9;
                    xring[bb2 * 16 + st][k] = v;
                }
            }
        }
        __syncwarp();
        #pragma unroll 1
        for (int j = 0; j < BK; j++) {
            const float2* xp = (const float2*)xring[j];
            float2 X0 = xp[0], X1 = xp[1], X2 = xp[2], X3 = xp[3], X4 = xp[4];
            #pragma unroll
            for (int q = 0; q < 3; q++) {
                float2 a = make_float2(bx[q], 0.f);
                a = ffma2(wx[q][0], X0, a); a = ffma2(wx[q][1], X1, a);
                a = ffma2(wx[q][2], X2, a); a = ffma2(wx[q][3], X3, a);
                a = ffma2(wx[q][4], X4, a);
                if (av[0] || true) { }
                if (xv[q]) xpart[0][j][xu[q]][xg[q]] = a.x + a.y;
            }
        }
    }
    __syncthreads();

    float cst = 0.f;   // cell state (W0: c1, W2: c2)
    const float2 ONE = make_float2(1.f, 1.f);

    // ================= main superstep loop =================
    #pragma unroll 1
    for (int s = 0; s <= NS + 2; s++) {
        if (w == 0) {
            // -------- L1 core: block s --------
            if (s < NS) {
                const int t0 = s * BK;
                const int sl = s & 1;
                #pragma unroll 2
                for (int j = 0; j < BK; j++) {
                    const int t = t0 + j;
                    const float4 xp = *((const float4*)&xpart[sl][j][uc][0]);
                    const float2* hp = (const float2*)h1r[(t + 31) & 31];
                    float2 e0 = make_float2(xp.x, 0.f), e1 = make_float2(xp.y, 0.f);
                    float2 e2 = make_float2(xp.z, 0.f), e3 = make_float2(xp.w, 0.f);
                    float2 o0 = make_float2(0.f, 0.f), o1 = o0, o2 = o0, o3 = o0;
                    #pragma unroll
                    for (int k = 0; k < 10; k += 2) {
                        const float2 a = hp[k], b = hp[k + 1];
                        e0 = ffma2(wh[0][k], a, e0); e1 = ffma2(wh[1][k], a, e1);
                        e2 = ffma2(wh[2][k], a, e2); e3 = ffma2(wh[3][k], a, e3);
                        o0 = ffma2(wh[0][k+1], b, o0); o1 = ffma2(wh[1][k+1], b, o1);
                        o2 = ffma2(wh[2][k+1], b, o2); o3 = ffma2(wh[3][k+1], b, o3);
                    }
                    e0 = ffma2(ONE, o0, e0); e1 = ffma2(ONE, o1, e1);
                    e2 = ffma2(ONE, o2, e2); e3 = ffma2(ONE, o3, e3);
                    const float si = sigm_f(e0.x + e0.y);
                    const float sf = sigm_f(e1.x + e1.y);
                    const float sg = tanh_f(e2.x + e2.y);
                    const float so = sigm_f(e3.x + e3.y);
                    cst = fmaf(sf, cst, si * sg);
                    const float h = so * tanh_f(cst);
                    if (lane < 20) h1r[t & 31][lane] = h;
                    __syncwarp();
                }
            }
        } else if (w == 1) {
            // -------- L2 pre (w_ih2·h1 + b2): block s-1 --------
            if (s >= 1 && s <= NS) {
                const int b = s - 1;
                const int t0 = b * BK;
                const int sl = b & 1;
                #pragma unroll 2
                for (int j = 0; j < BK; j++) {
                    const float2* hp = (const float2*)h1r[(t0 + j) & 31];
                    float2 A0 = make_float2(bb[0], 0.f), B0 = make_float2(0.f, 0.f);
                    float2 A1 = make_float2(bb[1], 0.f), B1 = B0;
                    float2 A2 = make_float2(bb[2], 0.f), B2 = B0;
                    #pragma unroll
                    for (int k = 0; k < 10; k += 2) {
                        const float2 a = hp[k], b2v = hp[k + 1];
                        A0 = ffma2(wi[0][k], a, A0); A1 = ffma2(wi[1][k], a, A1); A2 = ffma2(wi[2][k], a, A2);
                        B0 = ffma2(wi[0][k+1], b2v, B0); B1 = ffma2(wi[1][k+1], b2v, B1); B2 = ffma2(wi[2][k+1], b2v, B2);
                    }
                    A0 = ffma2(ONE, B0, A0); A1 = ffma2(ONE, B1, A1); A2 = ffma2(ONE, B2, A2);
                    apart[sl][j][au[0]][ag[0]] = A0.x + A0.y;
                    apart[sl][j][au[1]][ag[1]] = A1.x + A1.y;
                    if (av[2]) apart[sl][j][au[2]][ag[2]] = A2.x + A2.y;
                }
            }
        } else if (w == 2) {
            // -------- L2 core: block s-2 --------
            if (s >= 2 && s <= NS + 1) {
                const int b = s - 2;
                const int t0 = b * BK;
                const int sl = b & 1;
                #pragma unroll 2
                for (int j = 0; j < BK; j++) {
                    const int t = t0 + j;
                    const float4 ap = *((const float4*)&apart[sl][j][uc][0]);
                    const float2* hp = (const float2*)h2r[(t + 31) & 31];
                    float2 e0 = make_float2(ap.x, 0.f), e1 = make_float2(ap.y, 0.f);
                    float2 e2 = make_float2(ap.z, 0.f), e3 = make_float2(ap.w, 0.f);
                    float2 o0 = make_float2(0.f, 0.f), o1 = o0, o2 = o0, o3 = o0;
                    #pragma unroll
                    for (int k = 0; k < 10; k += 2) {
                        const float2 a = hp[k], b2v = hp[k + 1];
                        e0 = ffma2(wh[0][k], a, e0); e1 = ffma2(wh[1][k], a, e1);
                        e2 = ffma2(wh[2][k], a, e2); e3 = ffma2(wh[3][k], a, e3);
                        o0 = ffma2(wh[0][k+1], b2v, o0); o1 = ffma2(wh[1][k+1], b2v, o1);
                        o2 = ffma2(wh[2][k+1], b2v, o2); o3 = ffma2(wh[3][k+1], b2v, o3);
                    }
                    e0 = ffma2(ONE, o0, e0); e1 = ffma2(ONE, o1, e1);
                    e2 = ffma2(ONE, o2, e2); e3 = ffma2(ONE, o3, e3);
                    const float si = sigm_f(e0.x + e0.y);
                    const float sf = sigm_f(e1.x + e1.y);
                    const float sg = tanh_f(e2.x + e2.y);
                    const float so = sigm_f(e3.x + e3.y);
                    cst = fmaf(sf, cst, si * sg);
                    const float h = so * tanh_f(cst);
                    if (lane < 20) h2r[t & 31][lane] = h;
                    __syncwarp();
                }
            }
        } else {
            // -------- W3: x load (block s+2), xpart (block s+1), proj (block s-3) --------
            if (s + 2 <= NS - 1) {
                const int b2v = s + 2;
                const float* src = x + b2v * 144;
                #pragma unroll
                for (int i = 0; i < 5; i++) {
                    const int idx = lane + 32 * i;
                    if (idx < 144) {
                        const float v = __ldg(&src[idx]);
                        const int st = idx / 9, k = idx - st * 9;
                        xring[(b2v & 1) * 16 + st][k] = v;
                    }
                }
            }
            if (s + 1 <= NS - 1) {
                const int bp = s + 1;
                const int xb = (bp & 1) * 16;
                const int sl = bp & 1;
                #pragma unroll 2
                for (int j = 0; j < BK; j++) {
                    const float2* xp = (const float2*)xring[xb + j];
                    const float2 X0 = xp[0], X1 = xp[1], X2 = xp[2], X3 = xp[3], X4 = xp[4];
                    #pragma unroll
                    for (int q = 0; q < 3; q++) {
                        float2 a = make_float2(bx[q], 0.f);
                        float2 o = make_float2(0.f, 0.f);
                        a = ffma2(wx[q][0], X0, a); o = ffma2(wx[q][1], X1, o);
                        a = ffma2(wx[q][2], X2, a); o = ffma2(wx[q][3], X3, o);
                        a = ffma2(wx[q][4], X4, a);
                        a = ffma2(ONE, o, a);
                        if (xv[q]) xpart[sl][j][xu[q]][xg[q]] = a.x + a.y;
                    }
                }
            }
            if (s >= 3) {
                const int b = s - 3;
                const int t0 = b * BK;
                #pragma unroll 2
                for (int j = 0; j < BK; j++) {
                    const int t = t0 + j;
                    const float hv = (lane < 20) ? h2r[t & 31][lane] : 0.f;
                    float p = wpv * hv;
                    #pragma unroll
                    for (int o = 16; o; o >>= 1) p += __shfl_down_sync(0xffffffffu, p, o);
                    if (lane == 0) out[t] = p + bpv;
                }
            }
        }
        __syncthreads();
    }
}

extern "C" void kernel_launch(void* const* d_in, const int* in_sizes, int n_in,
                              void* d_out, int out_size) {
    (void)in_sizes; (void)n_in; (void)out_size;
    lstm_scan_kernel<<<1, 128>>>(
        (const float*)d_in[0],
        (const float*)d_in[1], (const float*)d_in[2], (const float*)d_in[3],
        (const float*)d_in[4], (const float*)d_in[5], (const float*)d_in[6],
        (const float*)d_in[7], (const float*)d_in[8],
        (float*)d_out);
}

// round 7
// speedup vs baseline: 2.0902x; 1.3558x over previous
#include <cuda_runtime.h>
#include <cstdint>

#define SEQ 262144
#define BK  16
#define NS  (SEQ / BK)   // 16384 supersteps

union F2U { float2 f; unsigned long long u; };
__device__ __forceinline__ float2 ffma2(float2 a, float2 b, float2 c) {
    F2U A, B, C, R; A.f = a; B.f = b; C.f = c;
    asm("fma.rn.f32x2 %0, %1, %2, %3;" : "=l"(R.u) : "l"(A.u), "l"(B.u), "l"(C.u));
    return R.f;
}
__device__ __forceinline__ float tanha(float x) {
    float r; asm("tanh.approx.f32 %0, %1;" : "=f"(r) : "f"(x)); return r;
}
__device__ __forceinline__ float sigm_f(float x) { return fmaf(tanha(x * 0.5f), 0.5f, 0.5f); }
__device__ __forceinline__ float tanh_f(float x) { return tanha(x); }

__global__ void __launch_bounds__(128, 1) lstm_scan_kernel(
    const float* __restrict__ x,
    const float* __restrict__ w_ih1, const float* __restrict__ w_hh1, const float* __restrict__ b1,
    const float* __restrict__ w_ih2, const float* __restrict__ w_hh2, const float* __restrict__ b2,
    const float* __restrict__ w_p,  const float* __restrict__ b_p,
    float* __restrict__ out)
{
    __shared__ float xring[32][12];                       // 2 blocks of x
    __shared__ __align__(16) float xpart[2][BK][20][4];   // b1 + w_ih1·x  (per step,unit,gate)
    __shared__ __align__(16) float apart[2][BK][20][4];   // b2 + w_ih2·h1
    __shared__ __align__(16) float h1r[32][24];           // rows 96B, 16B aligned
    __shared__ __align__(16) float h2r[32][24];

    const int tid  = threadIdx.x;
    const int w    = tid >> 5;
    const int lane = tid & 31;
    const int uc   = (lane < 20) ? lane : 19;

    // ---------------- per-warp resident weights ----------------
    float2 wh[4][10];               // W0: w_hh1 rows; W2: w_hh2 rows (gate g, unit uc)
    float2 wi[3][10]; float bb[3];  // W1: w_ih2 rows r = lane + 32q
    int    au[3], ag[3], av[3];
    float2 wx[3][5];  float bx[3];  // W3: w_ih1 rows
    int    xu[3], xg[3], xv[3];
    float  wpv = 0.f;

    if (w == 0 || w == 2) {
        const float* WH = (w == 0) ? w_hh1 : w_hh2;
        #pragma unroll
        for (int g = 0; g < 4; g++) {
            const int r = g * 20 + uc;
            const float2* row = (const float2*)(WH + r * 20);
            #pragma unroll
            for (int k = 0; k < 10; k++) wh[g][k] = row[k];
        }
    } else if (w == 1) {
        #pragma unroll
        for (int q = 0; q < 3; q++) {
            const int r  = lane + 32 * q;
            const int ok = (r < 80);
            const int rc = ok ? r : 79;
            const float2* row = (const float2*)(w_ih2 + rc * 20);
            #pragma unroll
            for (int k = 0; k < 10; k++) wi[q][k] = row[k];
            bb[q] = b2[rc];
            au[q] = rc % 20; ag[q] = rc / 20; av[q] = ok;
        }
    } else {
        #pragma unroll
        for (int q = 0; q < 3; q++) {
            const int r  = lane + 32 * q;
            const int ok = (r < 80);
            const int rc = ok ? r : 79;
            const float* row = w_ih1 + rc * 9;
            wx[q][0] = make_float2(row[0], row[1]);
            wx[q][1] = make_float2(row[2], row[3]);
            wx[q][2] = make_float2(row[4], row[5]);
            wx[q][3] = make_float2(row[6], row[7]);
            wx[q][4] = make_float2(row[8], 0.f);
            bx[q] = b1[rc];
            xu[q] = rc % 20; xg[q] = rc / 20; xv[q] = ok;
        }
        if (lane < 20) wpv = w_p[lane];
    }
    const float bpv = b_p[0];

    // ---------------- zero rings ----------------
    for (int i = tid; i < 32 * 24; i += 128) { ((float*)h1r)[i] = 0.f; ((float*)h2r)[i] = 0.f; }
    for (int i = tid; i < 32 * 12; i += 128) ((float*)xring)[i] = 0.f;
    __syncthreads();

    // ---------------- prologue: x blocks 0,1 then xpart block 0 ----------------
    if (w == 3) {
        #pragma unroll
        for (int bb2 = 0; bb2 < 2; bb2++) {
            const float* src = x + bb2 * 144;
            #pragma unroll
            for (int i = 0; i < 5; i++) {
                const int idx = lane + 32 * i;
                if (idx < 144) {
                    const float v = src[idx];
                    const int st = idx / 9, k = idx - st * 9;
                    xring[bb2 * 16 + st][k] = v;
                }
            }
        }
        __syncwarp();
        #pragma unroll 1
        for (int j = 0; j < BK; j++) {
            const float2* xp = (const float2*)xring[j];
            float2 X0 = xp[0], X1 = xp[1], X2 = xp[2], X3 = xp[3], X4 = xp[4];
            #pragma unroll
            for (int q = 0; q < 3; q++) {
                float2 a = make_float2(bx[q], 0.f);
                a = ffma2(wx[q][0], X0, a); a = ffma2(wx[q][1], X1, a);
                a = ffma2(wx[q][2], X2, a); a = ffma2(wx[q][3], X3, a);
                a = ffma2(wx[q][4], X4, a);
                if (xv[q]) xpart[0][j][xu[q]][xg[q]] = a.x + a.y;
            }
        }
    }
    __syncthreads();

    float cst = 0.f;   // cell state (W0: c1, W2: c2)
    const float2 ONE = make_float2(1.f, 1.f);

    // ================= main superstep loop =================
    #pragma unroll 1
    for (int s = 0; s <= NS + 2; s++) {
        if (w == 0) {
            // -------- L1 core: block s --------
            if (s < NS) {
                const int t0 = s * BK;
                const int sl = s & 1;
                #pragma unroll 2
                for (int j = 0; j < BK; j++) {
                    const int t = t0 + j;
                    const float4 xp = *((const float4*)&xpart[sl][j][uc][0]);
                    const float4* hp = (const float4*)h1r[(t + 31) & 31];
                    float2 e0 = make_float2(xp.x, 0.f), e1 = make_float2(xp.y, 0.f);
                    float2 e2 = make_float2(xp.z, 0.f), e3 = make_float2(xp.w, 0.f);
                    float2 o0 = make_float2(0.f, 0.f), o1 = o0, o2 = o0, o3 = o0;
                    #pragma unroll
                    for (int k4 = 0; k4 < 5; k4++) {
                        const float4 hv = hp[k4];
                        const float2 a = make_float2(hv.x, hv.y);
                        const float2 b = make_float2(hv.z, hv.w);
                        e0 = ffma2(wh[0][2*k4], a, e0); e1 = ffma2(wh[1][2*k4], a, e1);
                        e2 = ffma2(wh[2][2*k4], a, e2); e3 = ffma2(wh[3][2*k4], a, e3);
                        o0 = ffma2(wh[0][2*k4+1], b, o0); o1 = ffma2(wh[1][2*k4+1], b, o1);
                        o2 = ffma2(wh[2][2*k4+1], b, o2); o3 = ffma2(wh[3][2*k4+1], b, o3);
                    }
                    e0 = ffma2(ONE, o0, e0); e1 = ffma2(ONE, o1, e1);
                    e2 = ffma2(ONE, o2, e2); e3 = ffma2(ONE, o3, e3);
                    const float si = sigm_f(e0.x + e0.y);
                    const float sf = sigm_f(e1.x + e1.y);
                    const float sg = tanh_f(e2.x + e2.y);
                    const float so = sigm_f(e3.x + e3.y);
                    cst = fmaf(sf, cst, si * sg);
                    const float h = so * tanh_f(cst);
                    if (lane < 20) h1r[t & 31][lane] = h;
                    __syncwarp();
                }
            }
        } else if (w == 1) {
            // -------- L2 pre (w_ih2·h1 + b2): block s-1 --------
            if (s >= 1 && s <= NS) {
                const int b = s - 1;
                const int t0 = b * BK;
                const int sl = b & 1;
                #pragma unroll 2
                for (int j = 0; j < BK; j++) {
                    const float4* hp = (const float4*)h1r[(t0 + j) & 31];
                    float2 A0 = make_float2(bb[0], 0.f), B0 = make_float2(0.f, 0.f);
                    float2 A1 = make_float2(bb[1], 0.f), B1 = B0;
                    float2 A2 = make_float2(bb[2], 0.f), B2 = B0;
                    #pragma unroll
                    for (int k4 = 0; k4 < 5; k4++) {
                        const float4 hv = hp[k4];
                        const float2 a = make_float2(hv.x, hv.y);
                        const float2 b2v = make_float2(hv.z, hv.w);
                        A0 = ffma2(wi[0][2*k4], a, A0); A1 = ffma2(wi[1][2*k4], a, A1); A2 = ffma2(wi[2][2*k4], a, A2);
                        B0 = ffma2(wi[0][2*k4+1], b2v, B0); B1 = ffma2(wi[1][2*k4+1], b2v, B1); B2 = ffma2(wi[2][2*k4+1], b2v, B2);
                    }
                    A0 = ffma2(ONE, B0, A0); A1 = ffma2(ONE, B1, A1); A2 = ffma2(ONE, B2, A2);
                    apart[sl][j][au[0]][ag[0]] = A0.x + A0.y;
                    apart[sl][j][au[1]][ag[1]] = A1.x + A1.y;
                    if (av[2]) apart[sl][j][au[2]][ag[2]] = A2.x + A2.y;
                }
            }
        } else if (w == 2) {
            // -------- L2 core: block s-2 --------
            if (s >= 2 && s <= NS + 1) {
                const int b = s - 2;
                const int t0 = b * BK;
                const int sl = b & 1;
                #pragma unroll 2
                for (int j = 0; j < BK; j++) {
                    const int t = t0 + j;
                    const float4 ap = *((const float4*)&apart[sl][j][uc][0]);
                    const float4* hp = (const float4*)h2r[(t + 31) & 31];
                    float2 e0 = make_float2(ap.x, 0.f), e1 = make_float2(ap.y, 0.f);
                    float2 e2 = make_float2(ap.z, 0.f), e3 = make_float2(ap.w, 0.f);
                    float2 o0 = make_float2(0.f, 0.f), o1 = o0, o2 = o0, o3 = o0;
                    #pragma unroll
                    for (int k4 = 0; k4 < 5; k4++) {
                        const float4 hv = hp[k4];
                        const float2 a = make_float2(hv.x, hv.y);
                        const float2 b2v = make_float2(hv.z, hv.w);
                        e0 = ffma2(wh[0][2*k4], a, e0); e1 = ffma2(wh[1][2*k4], a, e1);
                        e2 = ffma2(wh[2][2*k4], a, e2); e3 = ffma2(wh[3][2*k4], a, e3);
                        o0 = ffma2(wh[0][2*k4+1], b2v, o0); o1 = ffma2(wh[1][2*k4+1], b2v, o1);
                        o2 = ffma2(wh[2][2*k4+1], b2v, o2); o3 = ffma2(wh[3][2*k4+1], b2v, o3);
                    }
                    e0 = ffma2(ONE, o0, e0); e1 = ffma2(ONE, o1, e1);
                    e2 = ffma2(ONE, o2, e2); e3 = ffma2(ONE, o3, e3);
                    const float si = sigm_f(e0.x + e0.y);
                    const float sf = sigm_f(e1.x + e1.y);
                    const float sg = tanh_f(e2.x + e2.y);
                    const float so = sigm_f(e3.x + e3.y);
                    cst = fmaf(sf, cst, si * sg);
                    const float h = so * tanh_f(cst);
                    if (lane < 20) h2r[t & 31][lane] = h;
                    __syncwarp();
                }
            }
        } else {
            // -------- W3: x load (block s+2), xpart (block s+1), proj (block s-3) --------
            if (s + 2 <= NS - 1) {
                const int b2v = s + 2;
                const float* src = x + b2v * 144;
                #pragma unroll
                for (int i = 0; i < 5; i++) {
                    const int idx = lane + 32 * i;
                    if (idx < 144) {
                        const float v = __ldg(&src[idx]);
                        const int st = idx / 9, k = idx - st * 9;
                        xring[(b2v & 1) * 16 + st][k] = v;
                    }
                }
            }
            if (s + 1 <= NS - 1) {
                const int bp = s + 1;
                const int xb = (bp & 1) * 16;
                const int sl = bp & 1;
                #pragma unroll 2
                for (int j = 0; j < BK; j++) {
                    const float2* xp = (const float2*)xring[xb + j];
                    const float2 X0 = xp[0], X1 = xp[1], X2 = xp[2], X3 = xp[3], X4 = xp[4];
                    #pragma unroll
                    for (int q = 0; q < 3; q++) {
                        float2 a = make_float2(bx[q], 0.f);
                        float2 o = make_float2(0.f, 0.f);
                        a = ffma2(wx[q][0], X0, a); o = ffma2(wx[q][1], X1, o);
                        a = ffma2(wx[q][2], X2, a); o = ffma2(wx[q][3], X3, o);
                        a = ffma2(wx[q][4], X4, a);
                        a = ffma2(ONE, o, a);
                        if (xv[q]) xpart[sl][j][xu[q]][xg[q]] = a.x + a.y;
                    }
                }
            }
            if (s >= 3) {
                const int b = s - 3;
                const int t0 = b * BK;
                #pragma unroll 2
                for (int j = 0; j < BK; j++) {
                    const int t = t0 + j;
                    const float hv = (lane < 20) ? h2r[t & 31][lane] : 0.f;
                    float p = wpv * hv;
                    #pragma unroll
                    for (int o = 16; o; o >>= 1) p += __shfl_down_sync(0xffffffffu, p, o);
                    if (lane == 0) out[t] = p + bpv;
                }
            }
        }
        __syncthreads();
    }
}

extern "C" void kernel_launch(void* const* d_in, const int* in_sizes, int n_in,
                              void* d_out, int out_size) {
    (void)in_sizes; (void)n_in; (void)out_size;
    lstm_scan_kernel<<<1, 128>>>(
        (const float*)d_in[0],
        (const float*)d_in[1], (const float*)d_in[2], (const float*)d_in[3],
        (const float*)d_in[4], (const float*)d_in[5], (const float*)d_in[6],
        (const float*)d_in[7], (const float*)d_in[8],
        (float*)d_out);
}